// round 10
// baseline (speedup 1.0000x reference)
#include <cuda_runtime.h>
#include <cstdint>

// FPS + gather, bit-exact vs JAX/XLA (distance = fma(dz,dz, fma(dx,dx, rn(dy*dy)))).
// B=8, N=131072, S=4096.
//
// R9 (on R8 skeleton): redux.sync argmax (max on value bits + min on candidate
// idx == first-occurrence argmax), coord prefetch overlapped with the final
// redux, and packed f32x2 distance math (per-lane IEEE-identical to the frozen
// scalar sequence; sub == add of negated operand, exact).
// Sync: single-hop all-to-all tagged release/acquire slots (tags strictly
// increase -> no ABA, one buffer). No atomics, no fences.

#define NB 8
#define NP 131072
#define NS 4096
#define CPB 16                 // CTAs per batch
#define NT 512                 // threads per CTA
#define ROUNDS (NS - 1)
#define PPC (NP / CPB)         // 8192 points per CTA

#define ADD2(r, a, b) asm("add.rn.f32x2 %0, %1, %2;" : "=l"(r) : "l"(a), "l"(b))
#define MUL2(r, a, b) asm("mul.rn.f32x2 %0, %1, %2;" : "=l"(r) : "l"(a), "l"(b))
#define FMA2(r, a, b, c) asm("fma.rn.f32x2 %0, %1, %2, %3;" : "=l"(r) : "l"(a), "l"(b), "l"(c))
#define PACK2(r, lo, hi) asm("mov.b64 %0, {%1, %2};" : "=l"(r) : "f"(lo), "f"(hi))
#define UNPACK2(lo, hi, r) asm("mov.b64 {%0, %1}, %2;" : "=f"(lo), "=f"(hi) : "l"(r))

__device__ float4 g_xyz[NB * NP];
struct __align__(2048) BSlots { unsigned long long key[CPB]; };
__device__ BSlots g_slots[NB];

__global__ void fps_prep_kernel(const float* __restrict__ pts) {
    if (blockIdx.x == 0 && threadIdx.x < NB * CPB) {
        g_slots[threadIdx.x / CPB].key[threadIdx.x % CPB] = 0ull;  // tag 0 < 1
    }
    int i = blockIdx.x * blockDim.x + threadIdx.x;
    int stride = gridDim.x * blockDim.x;
    for (; i < NB * NP; i += stride) {
        g_xyz[i] = make_float4(pts[3 * i + 0], pts[3 * i + 1], pts[3 * i + 2], 0.0f);
    }
}

__global__ void __launch_bounds__(NT, 1) fps_main_kernel(float* __restrict__ out) {
    const int b    = blockIdx.x / CPB;
    const int c    = blockIdx.x % CPB;
    const int tid  = threadIdx.x;
    const int lane = tid & 31;
    const int wid  = tid >> 5;
    const int base = c * PPC;
    const float4* __restrict__ P = g_xyz + b * NP;
    unsigned long long* __restrict__ slots = g_slots[b].key;

    // one-time: 16 points/thread -> 8 packed pairs per coordinate
    unsigned long long px2[8], py2[8], pz2[8];
    float md[16];
#pragma unroll
    for (int j = 0; j < 4; ++j) {
        const int e = j * NT + tid;
#pragma unroll
        for (int h = 0; h < 2; ++h) {
            float4 q0 = P[base + e * 4 + h * 2 + 0];
            float4 q1 = P[base + e * 4 + h * 2 + 1];
            PACK2(px2[j * 2 + h], q0.x, q1.x);
            PACK2(py2[j * 2 + h], q0.y, q1.y);
            PACK2(pz2[j * 2 + h], q0.z, q1.z);
        }
    }
#pragma unroll
    for (int i = 0; i < 16; ++i) md[i] = 1e10f;   // BIG

    __shared__ unsigned s_v[NT / 32];
    __shared__ unsigned s_i[NT / 32];
    __shared__ float s_win[3];

    // selection 0 is always index 0
    float4 p0 = P[0];
    float lx = p0.x, ly = p0.y, lz = p0.z;
    if (c == 0 && tid == 0) {
        out[(b * NS + 0) * 3 + 0] = lx;
        out[(b * NS + 0) * 3 + 1] = ly;
        out[(b * NS + 0) * 3 + 2] = lz;
    }

    const int tb = base + tid * 4;

    for (int r = 0; r < ROUNDS; ++r) {
        float bestv = -1.0f;
        int   besti = 0;

        // packed negated last point (exact: a-b == a+(-b))
        unsigned long long nlx2, nly2, nlz2;
        { float nx = -lx, ny = -ly, nz = -lz;
          PACK2(nlx2, nx, nx); PACK2(nly2, ny, ny); PACK2(nlz2, nz, nz); }

#pragma unroll
        for (int p = 0; p < 8; ++p) {
            const int j = p >> 1, h = p & 1;
            const int idx0 = tb + j * (NT * 4) + h * 2;
            unsigned long long dx2, dy2, dz2, s2;
            // per-lane: dx=sub(px,lx); dy=...; dz=...; d=fma(dz,dz,fma(dx,dx,mul(dy,dy)))
            ADD2(dx2, px2[p], nlx2);
            ADD2(dy2, py2[p], nly2);
            ADD2(dz2, pz2[p], nlz2);
            MUL2(s2, dy2, dy2);
            FMA2(s2, dx2, dx2, s2);
            FMA2(s2, dz2, dz2, s2);
            float d0, d1;
            UNPACK2(d0, d1, s2);
            float m0 = fminf(md[p * 2 + 0], d0);
            md[p * 2 + 0] = m0;
            if (m0 > bestv) { bestv = m0; besti = idx0; }
            float m1 = fminf(md[p * 2 + 1], d1);
            md[p * 2 + 1] = m1;
            if (m1 > bestv) { bestv = m1; besti = idx0 + 1; }
        }

        // warp argmax via redux: max on value bits (v>=0), min idx among ties
        unsigned vbits = __float_as_uint(bestv);
        unsigned vmaxw = __reduce_max_sync(0xffffffffu, vbits);
        unsigned candw = (vbits == vmaxw) ? (unsigned)besti : 0xFFFFFFFFu;
        unsigned iminw = __reduce_min_sync(0xffffffffu, candw);
        if (lane == 0) { s_v[wid] = vmaxw; s_i[wid] = iminw; }
        __syncthreads();

        if (wid == 0) {
            const unsigned long long tag = (unsigned long long)(r + 1);  // 13 bits

            unsigned vb = (lane < 16) ? s_v[lane] : 0u;
            unsigned ib = (lane < 16) ? s_i[lane] : 0xFFFFFFFFu;
            unsigned vmax = __reduce_max_sync(0xffffffffu, vb);
            unsigned cand = (vb == vmax) ? ib : 0xFFFFFFFFu;
            unsigned imin = __reduce_min_sync(0xffffffffu, cand);
            if (lane == 0) {
                unsigned long long slot =
                    ((unsigned long long)vmax << 30) |
                    ((unsigned long long)(0x1FFFFu - imin) << 13) | tag;
                asm volatile("st.release.gpu.global.b64 [%0], %1;"
                             :: "l"(&slots[c]), "l"(slot) : "memory");
            }

            // single-hop: poll all 16 slots (one lane each) until current tag
            unsigned long long k = 0ull;
            bool got = (lane >= CPB);
            do {
                if (!got) {
                    asm volatile("ld.acquire.gpu.global.b64 %0, [%1];"
                                 : "=l"(k) : "l"(&slots[lane]) : "memory");
                    got = ((k & 0x1FFFull) == tag);
                }
            } while (!__all_sync(0xffffffffu, got));

            unsigned pvb = (lane < CPB) ? (unsigned)(k >> 30) : 0u;
            unsigned pix = (lane < CPB)
                         ? (0x1FFFFu - (unsigned)((k >> 13) & 0x1FFFFull)) : 0xFFFFFFFFu;
            // prefetch this slot's candidate coords; overlaps with redux below
            float4 w4 = (lane < CPB) ? P[pix] : make_float4(0.f, 0.f, 0.f, 0.f);
            unsigned gvmax = __reduce_max_sync(0xffffffffu, pvb);
            unsigned gcand = (pvb == gvmax) ? pix : 0xFFFFFFFFu;
            unsigned gimin = __reduce_min_sync(0xffffffffu, gcand);
            unsigned wl = __ffs(__ballot_sync(0xffffffffu, gcand == gimin)) - 1u;
            float wx = __shfl_sync(0xffffffffu, w4.x, wl);
            float wy = __shfl_sync(0xffffffffu, w4.y, wl);
            float wz = __shfl_sync(0xffffffffu, w4.z, wl);
            if (lane == 0) {
                s_win[0] = wx; s_win[1] = wy; s_win[2] = wz;
                if (c == 0) {
                    out[(b * NS + r + 1) * 3 + 0] = wx;
                    out[(b * NS + r + 1) * 3 + 1] = wy;
                    out[(b * NS + r + 1) * 3 + 2] = wz;
                }
            }
        }
        __syncthreads();
        lx = s_win[0]; ly = s_win[1]; lz = s_win[2];
    }
}

extern "C" void kernel_launch(void* const* d_in, const int* in_sizes, int n_in,
                              void* d_out, int out_size) {
    const float* pts = (const float*)d_in[0];
    float* out = (float*)d_out;
    (void)in_sizes; (void)n_in; (void)out_size;

    fps_prep_kernel<<<512, 256>>>(pts);
    fps_main_kernel<<<NB * CPB, NT>>>(out);
}

// round 11
// speedup vs baseline: 2.0487x; 2.0487x over previous
#include <cuda_runtime.h>
#include <cstdint>

// FPS + gather, bit-exact vs JAX/XLA (distance = fma(dz,dz, fma(dx,dx, rn(dy*dy)))).
// B=8, N=131072, S=4096.
//
// R10 = R8 skeleton (scalar frozen math, u64-key shuffle reduces, single-hop
// tagged slots) with:
//  - ALL sync via volatile ld/st (slot word is self-contained value|idx|tag:
//    no ordering needed; acquire/release per poll was invalidating L1 and
//    queueing ahead of the release store at the LTS slice).
//  - winner-coord prefetch at detect time, overlapped with the final reduce
//    (kills the serial post-reduce gather RTT).

#define NB 8
#define NP 131072
#define NS 4096
#define CPB 16                 // CTAs per batch
#define NT 512                 // threads per CTA
#define ROUNDS (NS - 1)
#define PPC (NP / CPB)         // 8192 points per CTA

__device__ float4 g_xyz[NB * NP];
struct __align__(2048) BSlots { unsigned long long key[CPB]; };
__device__ BSlots g_slots[NB];

__global__ void fps_prep_kernel(const float* __restrict__ pts) {
    if (blockIdx.x == 0 && threadIdx.x < NB * CPB) {
        g_slots[threadIdx.x / CPB].key[threadIdx.x % CPB] = 0ull;  // tag 0 < 1
    }
    int i = blockIdx.x * blockDim.x + threadIdx.x;
    int stride = gridDim.x * blockDim.x;
    for (; i < NB * NP; i += stride) {
        g_xyz[i] = make_float4(pts[3 * i + 0], pts[3 * i + 1], pts[3 * i + 2], 0.0f);
    }
}

__global__ void __launch_bounds__(NT, 1) fps_main_kernel(float* __restrict__ out) {
    const int b    = blockIdx.x / CPB;
    const int c    = blockIdx.x % CPB;
    const int tid  = threadIdx.x;
    const int lane = tid & 31;
    const int wid  = tid >> 5;
    const int base = c * PPC;
    const float4* __restrict__ P = g_xyz + b * NP;
    unsigned long long* __restrict__ slots = g_slots[b].key;

    // one-time: 16 points/thread into registers
    float px[16], py[16], pz[16], md[16];
#pragma unroll
    for (int j = 0; j < 4; ++j) {
        const int e = j * NT + tid;
#pragma unroll
        for (int k = 0; k < 4; ++k) {
            float4 q = P[base + e * 4 + k];
            px[j * 4 + k] = q.x; py[j * 4 + k] = q.y; pz[j * 4 + k] = q.z;
        }
    }
#pragma unroll
    for (int i = 0; i < 16; ++i) md[i] = 1e10f;   // BIG

    __shared__ unsigned long long s_k[NT / 32];
    __shared__ float s_win[3];

    // selection 0 is always index 0
    float4 p0 = P[0];
    float lx = p0.x, ly = p0.y, lz = p0.z;
    if (c == 0 && tid == 0) {
        out[(b * NS + 0) * 3 + 0] = lx;
        out[(b * NS + 0) * 3 + 1] = ly;
        out[(b * NS + 0) * 3 + 2] = lz;
    }

    const int tb = base + tid * 4;

    for (int r = 0; r < ROUNDS; ++r) {
        float bestv = -1.0f;
        int   besti = 0;

#pragma unroll
        for (int j = 0; j < 4; ++j) {
#pragma unroll
            for (int k = 0; k < 4; ++k) {
                const int t   = j * 4 + k;
                const int idx = tb + j * (NT * 4) + k;
                // FROZEN arithmetic (rel_err 0.0): fma(dz,dz, fma(dx,dx, rn(dy*dy)))
                float dx = __fsub_rn(px[t], lx);
                float dy = __fsub_rn(py[t], ly);
                float dz = __fsub_rn(pz[t], lz);
                float d  = __fmaf_rn(dz, dz,
                           __fmaf_rn(dx, dx,
                           __fmul_rn(dy, dy)));
                float m  = fminf(md[t], d);
                md[t] = m;
                // per-thread ascending idx + strict '>' == first-occurrence argmax
                if (m > bestv) { bestv = m; besti = idx; }
            }
        }

        // pack: max(key) == argmax(v) with min-idx tiebreak (v>=0 -> bits monotonic)
        unsigned long long wkey =
            ((unsigned long long)__float_as_uint(bestv) << 17) |
            (unsigned)(0x1FFFF - besti);

        // warp reduce (down: lane0 gets max)
#pragma unroll
        for (int off = 16; off > 0; off >>= 1) {
            unsigned long long ok = __shfl_down_sync(0xffffffffu, wkey, off);
            if (ok > wkey) wkey = ok;
        }
        if (lane == 0) s_k[wid] = wkey;
        __syncthreads();

        if (wid == 0) {
            const unsigned long long tag = (unsigned long long)(r + 1);  // 13 bits

            // CTA reduce over 16 warp keys
            unsigned long long kk = (lane < 16) ? s_k[lane] : 0ull;
#pragma unroll
            for (int off = 8; off > 0; off >>= 1) {
                unsigned long long ok = __shfl_down_sync(0xffffffffu, kk, off);
                if (ok > kk) kk = ok;
            }
            if (lane == 0) {
                unsigned long long slot = (kk << 13) | tag;
                asm volatile("st.volatile.global.b64 [%0], %1;"
                             :: "l"(&slots[c]), "l"(slot) : "memory");
            }

            // single-hop: poll all 16 slots (one lane each) until current tag;
            // prefetch candidate coords the moment a lane's tag matches
            unsigned long long k = 0ull;
            float4 w4 = make_float4(0.f, 0.f, 0.f, 0.f);
            bool got = (lane >= CPB);
            do {
                if (!got) {
                    asm volatile("ld.volatile.global.b64 %0, [%1];"
                                 : "=l"(k) : "l"(&slots[lane]) : "memory");
                    if ((k & 0x1FFFull) == tag) {
                        got = true;
                        w4 = P[0x1FFFF - (int)((k >> 13) & 0x1FFFFull)];  // overlap
                    }
                }
            } while (!__all_sync(0xffffffffu, got));

            // cross-CTA reduce (bfly so every lane has the max), then pick lane
            unsigned long long mykey = (lane < CPB) ? (k >> 13) : 0ull;
            unsigned long long k2 = mykey;
#pragma unroll
            for (int off = 8; off > 0; off >>= 1) {
                unsigned long long ok = __shfl_xor_sync(0xffffffffu, k2, off);
                if (ok > k2) k2 = ok;
            }
            unsigned wl = __ffs(__ballot_sync(0xffffffffu,
                                 (lane < CPB) && (mykey == k2))) - 1u;
            float wx = __shfl_sync(0xffffffffu, w4.x, wl);
            float wy = __shfl_sync(0xffffffffu, w4.y, wl);
            float wz = __shfl_sync(0xffffffffu, w4.z, wl);
            if (lane == 0) {
                s_win[0] = wx; s_win[1] = wy; s_win[2] = wz;
                if (c == 0) {
                    out[(b * NS + r + 1) * 3 + 0] = wx;
                    out[(b * NS + r + 1) * 3 + 1] = wy;
                    out[(b * NS + r + 1) * 3 + 2] = wz;
                }
            }
        }
        __syncthreads();
        lx = s_win[0]; ly = s_win[1]; lz = s_win[2];
    }
}

extern "C" void kernel_launch(void* const* d_in, const int* in_sizes, int n_in,
                              void* d_out, int out_size) {
    const float* pts = (const float*)d_in[0];
    float* out = (float*)d_out;
    (void)in_sizes; (void)n_in; (void)out_size;

    fps_prep_kernel<<<512, 256>>>(pts);
    fps_main_kernel<<<NB * CPB, NT>>>(out);
}

// round 12
// speedup vs baseline: 2.3542x; 1.1491x over previous
#include <cuda_runtime.h>
#include <cstdint>

// FPS + gather, bit-exact vs JAX/XLA (distance = fma(dz,dz, fma(dx,dx, rn(dy*dy)))).
// B=8, N=131072, S=4096.
//
// R11: per-batch 16-CTA cluster (nonportable size). Cross-CTA exchange via
// DSMEM mailboxes: each CTA stores its tagged key into all 16 peers' smem
// (st.relaxed.cluster, ~215cyc flight); every CTA polls its OWN smem (LDS
// ~30cyc/iter) instead of L2 (~260). No fences (single self-contained tagged
// word), no L2 in the loop. Coords in registers since R7, so cluster launch
// no longer hurts (R4's failure was L1-flush of a memory-resident loop).
// Fallback: exact R10 kernel if the 16-wide cluster config is not viable
// (cudaOccupancyMaxActiveClusters query, deterministic, capture-safe).

#define NB 8
#define NP 131072
#define NS 4096
#define CPB 16                 // CTAs per batch == cluster size
#define NT 512                 // threads per CTA
#define ROUNDS (NS - 1)
#define PPC (NP / CPB)         // 8192 points per CTA

__device__ float4 g_xyz[NB * NP];
struct __align__(2048) BSlots { unsigned long long key[CPB]; };
__device__ BSlots g_slots[NB];   // used by fallback path only

__global__ void fps_prep_kernel(const float* __restrict__ pts) {
    if (blockIdx.x == 0 && threadIdx.x < NB * CPB) {
        g_slots[threadIdx.x / CPB].key[threadIdx.x % CPB] = 0ull;  // tag 0 < 1
    }
    int i = blockIdx.x * blockDim.x + threadIdx.x;
    int stride = gridDim.x * blockDim.x;
    for (; i < NB * NP; i += stride) {
        g_xyz[i] = make_float4(pts[3 * i + 0], pts[3 * i + 1], pts[3 * i + 2], 0.0f);
    }
}

__device__ __forceinline__ uint32_t smem_u32(const void* p) {
    uint32_t a;
    asm("{ .reg .u64 t; cvta.to.shared.u64 t, %1; cvt.u32.u64 %0, t; }" : "=r"(a) : "l"(p));
    return a;
}

// ===================== cluster kernel (DSMEM mailboxes) =====================
__global__ void __launch_bounds__(NT, 1) fps_cluster_kernel(float* __restrict__ out) {
    const int b    = blockIdx.x / CPB;
    const int c    = blockIdx.x % CPB;     // == cluster rank
    const int tid  = threadIdx.x;
    const int lane = tid & 31;
    const int wid  = tid >> 5;
    const int base = c * PPC;
    const float4* __restrict__ P = g_xyz + b * NP;

    float px[16], py[16], pz[16], md[16];
#pragma unroll
    for (int j = 0; j < 4; ++j) {
        const int e = j * NT + tid;
#pragma unroll
        for (int k = 0; k < 4; ++k) {
            float4 q = P[base + e * 4 + k];
            px[j * 4 + k] = q.x; py[j * 4 + k] = q.y; pz[j * 4 + k] = q.z;
        }
    }
#pragma unroll
    for (int i = 0; i < 16; ++i) md[i] = 1e10f;   // BIG

    __shared__ unsigned long long s_k[NT / 32];
    __shared__ __align__(8) unsigned long long s_mb[CPB];   // mailboxes (one per sender rank)
    __shared__ float s_win[3];

    if (tid < CPB) s_mb[tid] = 0ull;   // tag 0 never matches r+1
    __syncthreads();
    asm volatile("barrier.cluster.arrive.aligned;" ::: "memory");
    asm volatile("barrier.cluster.wait.aligned;"   ::: "memory");

    const uint32_t mb_base = smem_u32(s_mb);

    float4 p0 = P[0];
    float lx = p0.x, ly = p0.y, lz = p0.z;
    if (c == 0 && tid == 0) {
        out[(b * NS + 0) * 3 + 0] = lx;
        out[(b * NS + 0) * 3 + 1] = ly;
        out[(b * NS + 0) * 3 + 2] = lz;
    }

    const int tb = base + tid * 4;

    for (int r = 0; r < ROUNDS; ++r) {
        float bestv = -1.0f;
        int   besti = 0;

#pragma unroll
        for (int j = 0; j < 4; ++j) {
#pragma unroll
            for (int k = 0; k < 4; ++k) {
                const int t   = j * 4 + k;
                const int idx = tb + j * (NT * 4) + k;
                // FROZEN arithmetic (rel_err 0.0): fma(dz,dz, fma(dx,dx, rn(dy*dy)))
                float dx = __fsub_rn(px[t], lx);
                float dy = __fsub_rn(py[t], ly);
                float dz = __fsub_rn(pz[t], lz);
                float d  = __fmaf_rn(dz, dz,
                           __fmaf_rn(dx, dx,
                           __fmul_rn(dy, dy)));
                float m  = fminf(md[t], d);
                md[t] = m;
                if (m > bestv) { bestv = m; besti = idx; }
            }
        }

        unsigned long long wkey =
            ((unsigned long long)__float_as_uint(bestv) << 17) |
            (unsigned)(0x1FFFF - besti);
#pragma unroll
        for (int off = 16; off > 0; off >>= 1) {
            unsigned long long ok = __shfl_down_sync(0xffffffffu, wkey, off);
            if (ok > wkey) wkey = ok;
        }
        if (lane == 0) s_k[wid] = wkey;
        __syncthreads();

        if (wid == 0) {
            const unsigned long long tag = (unsigned long long)(r + 1);  // 13 bits

            // CTA reduce (bfly: all lanes end with the CTA key)
            unsigned long long kk = (lane < 16) ? s_k[lane] : 0ull;
#pragma unroll
            for (int off = 8; off > 0; off >>= 1) {
                unsigned long long ok = __shfl_xor_sync(0xffffffffu, kk, off);
                if (ok > kk) kk = ok;
            }

            // publish: lane i stores my tagged key into peer i's mailbox [c]
            if (lane < CPB) {
                uint32_t la = mb_base + (uint32_t)c * 8u;
                uint32_t ra;
                asm("mapa.shared::cluster.u32 %0, %1, %2;" : "=r"(ra) : "r"(la), "r"(lane));
                unsigned long long w = (kk << 13) | tag;
                asm volatile("st.relaxed.cluster.shared::cluster.b64 [%0], %1;"
                             :: "r"(ra), "l"(w) : "memory");
            }

            // poll OWN mailboxes (LDS-speed); prefetch candidate coords on detect
            unsigned long long k = 0ull;
            float4 w4 = make_float4(0.f, 0.f, 0.f, 0.f);
            bool got = (lane >= CPB);
            const uint32_t pa = mb_base + (uint32_t)(lane & 15) * 8u;
            do {
                if (!got) {
                    asm volatile("ld.volatile.shared.b64 %0, [%1];" : "=l"(k) : "r"(pa));
                    if ((k & 0x1FFFull) == tag) {
                        got = true;
                        w4 = P[0x1FFFF - (int)((k >> 13) & 0x1FFFFull)];
                    }
                }
            } while (!__all_sync(0xffffffffu, got));

            unsigned long long mykey = (lane < CPB) ? (k >> 13) : 0ull;
            unsigned long long k2 = mykey;
#pragma unroll
            for (int off = 8; off > 0; off >>= 1) {
                unsigned long long ok = __shfl_xor_sync(0xffffffffu, k2, off);
                if (ok > k2) k2 = ok;
            }
            unsigned wl = __ffs(__ballot_sync(0xffffffffu,
                                 (lane < CPB) && (mykey == k2))) - 1u;
            float wx = __shfl_sync(0xffffffffu, w4.x, wl);
            float wy = __shfl_sync(0xffffffffu, w4.y, wl);
            float wz = __shfl_sync(0xffffffffu, w4.z, wl);
            if (lane == 0) {
                s_win[0] = wx; s_win[1] = wy; s_win[2] = wz;
                if (c == 0) {
                    out[(b * NS + r + 1) * 3 + 0] = wx;
                    out[(b * NS + r + 1) * 3 + 1] = wy;
                    out[(b * NS + r + 1) * 3 + 2] = wz;
                }
            }
        }
        __syncthreads();
        lx = s_win[0]; ly = s_win[1]; lz = s_win[2];
    }

    asm volatile("barrier.cluster.arrive.aligned;" ::: "memory");
    asm volatile("barrier.cluster.wait.aligned;"   ::: "memory");
}

// ===================== fallback kernel (exact R10) =====================
__global__ void __launch_bounds__(NT, 1) fps_fallback_kernel(float* __restrict__ out) {
    const int b    = blockIdx.x / CPB;
    const int c    = blockIdx.x % CPB;
    const int tid  = threadIdx.x;
    const int lane = tid & 31;
    const int wid  = tid >> 5;
    const int base = c * PPC;
    const float4* __restrict__ P = g_xyz + b * NP;
    unsigned long long* __restrict__ slots = g_slots[b].key;

    float px[16], py[16], pz[16], md[16];
#pragma unroll
    for (int j = 0; j < 4; ++j) {
        const int e = j * NT + tid;
#pragma unroll
        for (int k = 0; k < 4; ++k) {
            float4 q = P[base + e * 4 + k];
            px[j * 4 + k] = q.x; py[j * 4 + k] = q.y; pz[j * 4 + k] = q.z;
        }
    }
#pragma unroll
    for (int i = 0; i < 16; ++i) md[i] = 1e10f;

    __shared__ unsigned long long s_k[NT / 32];
    __shared__ float s_win[3];

    float4 p0 = P[0];
    float lx = p0.x, ly = p0.y, lz = p0.z;
    if (c == 0 && tid == 0) {
        out[(b * NS + 0) * 3 + 0] = lx;
        out[(b * NS + 0) * 3 + 1] = ly;
        out[(b * NS + 0) * 3 + 2] = lz;
    }

    const int tb = base + tid * 4;

    for (int r = 0; r < ROUNDS; ++r) {
        float bestv = -1.0f;
        int   besti = 0;
#pragma unroll
        for (int j = 0; j < 4; ++j) {
#pragma unroll
            for (int k = 0; k < 4; ++k) {
                const int t   = j * 4 + k;
                const int idx = tb + j * (NT * 4) + k;
                float dx = __fsub_rn(px[t], lx);
                float dy = __fsub_rn(py[t], ly);
                float dz = __fsub_rn(pz[t], lz);
                float d  = __fmaf_rn(dz, dz,
                           __fmaf_rn(dx, dx,
                           __fmul_rn(dy, dy)));
                float m  = fminf(md[t], d);
                md[t] = m;
                if (m > bestv) { bestv = m; besti = idx; }
            }
        }

        unsigned long long wkey =
            ((unsigned long long)__float_as_uint(bestv) << 17) |
            (unsigned)(0x1FFFF - besti);
#pragma unroll
        for (int off = 16; off > 0; off >>= 1) {
            unsigned long long ok = __shfl_down_sync(0xffffffffu, wkey, off);
            if (ok > wkey) wkey = ok;
        }
        if (lane == 0) s_k[wid] = wkey;
        __syncthreads();

        if (wid == 0) {
            const unsigned long long tag = (unsigned long long)(r + 1);
            unsigned long long kk = (lane < 16) ? s_k[lane] : 0ull;
#pragma unroll
            for (int off = 8; off > 0; off >>= 1) {
                unsigned long long ok = __shfl_down_sync(0xffffffffu, kk, off);
                if (ok > kk) kk = ok;
            }
            if (lane == 0) {
                unsigned long long slot = (kk << 13) | tag;
                asm volatile("st.volatile.global.b64 [%0], %1;"
                             :: "l"(&slots[c]), "l"(slot) : "memory");
            }

            unsigned long long k = 0ull;
            float4 w4 = make_float4(0.f, 0.f, 0.f, 0.f);
            bool got = (lane >= CPB);
            do {
                if (!got) {
                    asm volatile("ld.volatile.global.b64 %0, [%1];"
                                 : "=l"(k) : "l"(&slots[lane]) : "memory");
                    if ((k & 0x1FFFull) == tag) {
                        got = true;
                        w4 = P[0x1FFFF - (int)((k >> 13) & 0x1FFFFull)];
                    }
                }
            } while (!__all_sync(0xffffffffu, got));

            unsigned long long mykey = (lane < CPB) ? (k >> 13) : 0ull;
            unsigned long long k2 = mykey;
#pragma unroll
            for (int off = 8; off > 0; off >>= 1) {
                unsigned long long ok = __shfl_xor_sync(0xffffffffu, k2, off);
                if (ok > k2) k2 = ok;
            }
            unsigned wl = __ffs(__ballot_sync(0xffffffffu,
                                 (lane < CPB) && (mykey == k2))) - 1u;
            float wx = __shfl_sync(0xffffffffu, w4.x, wl);
            float wy = __shfl_sync(0xffffffffu, w4.y, wl);
            float wz = __shfl_sync(0xffffffffu, w4.z, wl);
            if (lane == 0) {
                s_win[0] = wx; s_win[1] = wy; s_win[2] = wz;
                if (c == 0) {
                    out[(b * NS + r + 1) * 3 + 0] = wx;
                    out[(b * NS + r + 1) * 3 + 1] = wy;
                    out[(b * NS + r + 1) * 3 + 2] = wz;
                }
            }
        }
        __syncthreads();
        lx = s_win[0]; ly = s_win[1]; lz = s_win[2];
    }
}

extern "C" void kernel_launch(void* const* d_in, const int* in_sizes, int n_in,
                              void* d_out, int out_size) {
    const float* pts = (const float*)d_in[0];
    float* out = (float*)d_out;
    (void)in_sizes; (void)n_in; (void)out_size;

    fps_prep_kernel<<<512, 256>>>(pts);

    // deterministic capability check (capture-safe query APIs, no allocation)
    cudaFuncSetAttribute(fps_cluster_kernel,
                         cudaFuncAttributeNonPortableClusterSizeAllowed, 1);
    cudaLaunchConfig_t cfg = {};
    cfg.gridDim  = dim3(NB * CPB, 1, 1);
    cfg.blockDim = dim3(NT, 1, 1);
    cfg.dynamicSmemBytes = 0;
    cfg.stream = 0;
    cudaLaunchAttribute at[1];
    at[0].id = cudaLaunchAttributeClusterDimension;
    at[0].val.clusterDim.x = CPB;
    at[0].val.clusterDim.y = 1;
    at[0].val.clusterDim.z = 1;
    cfg.attrs = at;
    cfg.numAttrs = 1;

    int nclu = 0;
    cudaError_t qe = cudaOccupancyMaxActiveClusters(&nclu, fps_cluster_kernel, &cfg);
    if (qe == cudaSuccess && nclu >= NB) {
        cudaLaunchKernelEx(&cfg, fps_cluster_kernel, out);
    } else {
        (void)cudaGetLastError();   // clear query error; take proven path
        fps_fallback_kernel<<<NB * CPB, NT>>>(out);
    }
}